// round 1
// baseline (speedup 1.0000x reference)
#include <cuda_runtime.h>
#include <cstdint>

#define N_NODES 100000
#define N_EDGES 600000
#define NET 3
#define NL 3
#define D 128
#define EPS 1e-5f

// -------- scratch (static device globals; no allocation) --------
__device__ float d_h[(size_t)N_NODES * D];      // hidden state between layers
__device__ float d_acc[(size_t)N_NODES * D];    // per-layer accumulator (pre-BN)
__device__ float d_neigh[(size_t)N_NODES * D];  // per-etype neighbor sum
__device__ float d_invdeg[NET * N_NODES];       // 1/clip(deg,1) per etype
__device__ float d_stats[2 * D];                // col sums / sumsq for BN

// ============================ utility kernels ============================

__global__ void zero_neigh_kernel() {
    size_t i = (size_t)blockIdx.x * blockDim.x + threadIdx.x;
    size_t n4 = (size_t)N_NODES * D / 4;
    if (i < n4) reinterpret_cast<float4*>(d_neigh)[i] = make_float4(0.f, 0.f, 0.f, 0.f);
}

__global__ void zero_deg_kernel() {
    int i = blockIdx.x * blockDim.x + threadIdx.x;
    if (i < NET * N_NODES) d_invdeg[i] = 0.f;
}

__global__ void zero_stats_kernel() {
    int i = threadIdx.x;
    if (i < 2 * D) d_stats[i] = 0.f;
}

__global__ void deg_count_kernel(const int* __restrict__ dst) {
    int idx = blockIdx.x * blockDim.x + threadIdx.x;
    if (idx >= NET * N_EDGES) return;
    int k = idx / N_EDGES;
    int d = __ldg(dst + idx);
    atomicAdd(&d_invdeg[k * N_NODES + d], 1.0f);
}

__global__ void deg_invert_kernel() {
    int i = blockIdx.x * blockDim.x + threadIdx.x;
    if (i < NET * N_NODES) d_invdeg[i] = 1.0f / fmaxf(d_invdeg[i], 1.0f);
}

// ============================ scatter (gather src rows, atomic-add to dst) ============================
// one warp per edge: 32 lanes x float4 = 128 floats
__global__ void scatter_kernel(const float* __restrict__ x, int use_x,
                               const int* __restrict__ src, const int* __restrict__ dst) {
    const float* hin = use_x ? x : d_h;
    int w = (blockIdx.x * blockDim.x + threadIdx.x) >> 5;
    int lane = threadIdx.x & 31;
    if (w >= N_EDGES) return;
    int s = __ldg(src + w);
    int d = __ldg(dst + w);
    float4 v = *reinterpret_cast<const float4*>(hin + (size_t)s * D + lane * 4);
    float* p = d_neigh + (size_t)d * D + lane * 4;
    asm volatile("red.global.add.v4.f32 [%0], {%1,%2,%3,%4};"
                 :: "l"(p), "f"(v.x), "f"(v.y), "f"(v.z), "f"(v.w)
                 : "memory");
}

// ============================ fused SGEMM ============================
// acc[ k==0 ? = : += ] relu?( [hin | neigh*invdeg] @ [Ws ; Wn] + bias )
// BM=128, BN=128(all), BK=16, 256 threads, 8x8 per thread
#define BM 128
#define BK 16

__global__ void __launch_bounds__(256, 2)
gemm_fused_kernel(const float* __restrict__ x, int use_x,
                  const float* __restrict__ Wself, const float* __restrict__ Wneigh,
                  const float* __restrict__ bias, int etype,
                  int accumulate, int do_relu) {
    const float* hin = use_x ? x : d_h;

    __shared__ float As[BK][BM + 4];
    __shared__ float Bs[BK][D];
    __shared__ float invd_s[BM];

    int tid = threadIdx.x;
    int m0 = blockIdx.x * BM;
    int tx = tid & 15;        // 0..15 -> cols
    int ty = tid >> 4;        // 0..15 -> rows

    if (tid < BM) {
        int r = m0 + tid;
        invd_s[tid] = (r < N_NODES) ? d_invdeg[etype * N_NODES + r] : 0.f;
    }

    float accr[8][8];
#pragma unroll
    for (int i = 0; i < 8; i++)
#pragma unroll
        for (int j = 0; j < 8; j++) accr[i][j] = 0.f;

    for (int kt = 0; kt < 2 * D; kt += BK) {
        bool neigh_phase = (kt >= D);
        int kk = neigh_phase ? (kt - D) : kt;

        __syncthreads();  // previous tile's compute done before overwrite

        // ---- load A tile (BM x BK), store transposed As[k][m] ----
#pragma unroll
        for (int j = 0; j < 2; j++) {
            int idx = tid * 2 + j;         // 0..511
            int row = idx >> 2;            // 0..127
            int c4 = (idx & 3) * 4;        // 0,4,8,12
            int gr = m0 + row;
            float4 v = make_float4(0.f, 0.f, 0.f, 0.f);
            if (gr < N_NODES) {
                const float* srcp = neigh_phase
                    ? (d_neigh + (size_t)gr * D + kk + c4)
                    : (hin + (size_t)gr * D + kk + c4);
                v = *reinterpret_cast<const float4*>(srcp);
                if (neigh_phase) {
                    float sc = invd_s[row];
                    v.x *= sc; v.y *= sc; v.z *= sc; v.w *= sc;
                }
            }
            As[c4 + 0][row] = v.x;
            As[c4 + 1][row] = v.y;
            As[c4 + 2][row] = v.z;
            As[c4 + 3][row] = v.w;
        }

        // ---- load B tile (BK x 128) ----
        const float* W = neigh_phase ? Wneigh : Wself;
#pragma unroll
        for (int j = 0; j < 2; j++) {
            int idx = tid * 2 + j;         // 0..511
            int row = idx >> 5;            // 0..15
            int c4 = (idx & 31) * 4;       // 0..124
            float4 v = *reinterpret_cast<const float4*>(W + (size_t)(kk + row) * D + c4);
            *reinterpret_cast<float4*>(&Bs[row][c4]) = v;
        }
        __syncthreads();

        // ---- compute ----
#pragma unroll
        for (int k = 0; k < BK; k++) {
            float a[8], bb[8];
#pragma unroll
            for (int i = 0; i < 8; i++) a[i] = As[k][ty * 8 + i];
#pragma unroll
            for (int j = 0; j < 8; j++) bb[j] = Bs[k][tx * 8 + j];
#pragma unroll
            for (int i = 0; i < 8; i++)
#pragma unroll
                for (int j = 0; j < 8; j++)
                    accr[i][j] = fmaf(a[i], bb[j], accr[i][j]);
        }
    }

    // ---- epilogue: bias, relu, accumulate into d_acc ----
#pragma unroll
    for (int i = 0; i < 8; i++) {
        int gm = m0 + ty * 8 + i;
        if (gm < N_NODES) {
#pragma unroll
            for (int j = 0; j < 8; j += 4) {
                int n = tx * 8 + j;
                float4 o;
                o.x = accr[i][j + 0] + __ldg(bias + n + 0);
                o.y = accr[i][j + 1] + __ldg(bias + n + 1);
                o.z = accr[i][j + 2] + __ldg(bias + n + 2);
                o.w = accr[i][j + 3] + __ldg(bias + n + 3);
                if (do_relu) {
                    o.x = fmaxf(o.x, 0.f); o.y = fmaxf(o.y, 0.f);
                    o.z = fmaxf(o.z, 0.f); o.w = fmaxf(o.w, 0.f);
                }
                float* p = d_acc + (size_t)gm * D + n;
                if (accumulate) {
                    float4 c = *reinterpret_cast<float4*>(p);
                    o.x += c.x; o.y += c.y; o.z += c.z; o.w += c.w;
                }
                *reinterpret_cast<float4*>(p) = o;
            }
        }
    }
}

// ============================ BatchNorm ============================

__global__ void bn_reduce_kernel() {
    int col = threadIdx.x;  // 128 threads
    int nblocks = gridDim.x;
    int rows_per = (N_NODES + nblocks - 1) / nblocks;
    int r0 = blockIdx.x * rows_per;
    int r1 = min(r0 + rows_per, N_NODES);
    float s = 0.f, sq = 0.f;
    for (int r = r0; r < r1; r++) {
        float v = d_acc[(size_t)r * D + col];
        s += v;
        sq = fmaf(v, v, sq);
    }
    atomicAdd(&d_stats[col], s);
    atomicAdd(&d_stats[D + col], sq);
}

__global__ void bn_norm_kernel(const float* __restrict__ gamma,
                               const float* __restrict__ beta,
                               float* __restrict__ outp, int write_out) {
    __shared__ float scale_s[D];
    __shared__ float shift_s[D];
    if (threadIdx.x < D) {
        int c = threadIdx.x;
        float mu = d_stats[c] * (1.0f / N_NODES);
        float var = d_stats[D + c] * (1.0f / N_NODES) - mu * mu;
        float sc = __ldg(gamma + c) * rsqrtf(var + EPS);
        scale_s[c] = sc;
        shift_s[c] = __ldg(beta + c) - mu * sc;
    }
    __syncthreads();
    float* dst = write_out ? outp : d_h;
    size_t i = (size_t)blockIdx.x * blockDim.x + threadIdx.x;
    size_t n4 = (size_t)N_NODES * D / 4;
    if (i >= n4) return;
    int col = (int)((i * 4) & (D - 1));
    float4 v = reinterpret_cast<const float4*>(d_acc)[i];
    float4 o;
    o.x = v.x * scale_s[col + 0] + shift_s[col + 0];
    o.y = v.y * scale_s[col + 1] + shift_s[col + 1];
    o.z = v.z * scale_s[col + 2] + shift_s[col + 2];
    o.w = v.w * scale_s[col + 3] + shift_s[col + 3];
    reinterpret_cast<float4*>(dst)[i] = o;
}

// ============================ launch ============================

extern "C" void kernel_launch(void* const* d_in, const int* in_sizes, int n_in,
                              void* d_out, int out_size) {
    const float* x     = (const float*)d_in[0];
    const int*   src   = (const int*)d_in[1];   // [3][600000]
    const int*   dst   = (const int*)d_in[2];   // [3][600000]
    const float* Ws    = (const float*)d_in[3]; // [3][3][128][128]
    const float* Wn    = (const float*)d_in[4]; // [3][3][128][128]
    const float* bias  = (const float*)d_in[5]; // [3][3][128]
    const float* gamma = (const float*)d_in[6]; // [3][128]
    const float* beta  = (const float*)d_in[7]; // [3][128]
    float* out = (float*)d_out;

    // ---- degrees (recomputed every call; deterministic work) ----
    {
        int n = NET * N_NODES;
        zero_deg_kernel<<<(n + 255) / 256, 256>>>();
        int ne = NET * N_EDGES;
        deg_count_kernel<<<(ne + 255) / 256, 256>>>(dst);
        deg_invert_kernel<<<(n + 255) / 256, 256>>>();
    }

    const int gemm_blocks = (N_NODES + BM - 1) / BM;            // 782
    const int neigh4 = N_NODES * D / 4;                         // 3.2M
    const int scatter_blocks = (N_EDGES * 32 + 255) / 256;      // 75000
    const int bn4_blocks = (N_NODES * D / 4 + 255) / 256;

    for (int l = 0; l < NL; l++) {
        int use_x = (l == 0);
        int do_relu = (l < NL - 1);
        for (int k = 0; k < NET; k++) {
            zero_neigh_kernel<<<(neigh4 + 255) / 256, 256>>>();
            scatter_kernel<<<scatter_blocks, 256>>>(x, use_x,
                                                    src + k * N_EDGES,
                                                    dst + k * N_EDGES);
            gemm_fused_kernel<<<gemm_blocks, 256>>>(
                x, use_x,
                Ws + (size_t)(l * NET + k) * D * D,
                Wn + (size_t)(l * NET + k) * D * D,
                bias + (size_t)(l * NET + k) * D,
                k, /*accumulate=*/(k > 0), do_relu);
        }
        zero_stats_kernel<<<1, 256>>>();
        bn_reduce_kernel<<<512, 128>>>();
        bn_norm_kernel<<<bn4_blocks, 256>>>(gamma + l * D, beta + l * D,
                                            out, /*write_out=*/(l == NL - 1));
    }
}

// round 2
// speedup vs baseline: 1.0081x; 1.0081x over previous
#include <cuda_runtime.h>
#include <cstdint>

#define N_NODES 100000
#define N_EDGES 600000
#define NET 3
#define NL 3
#define D 128
#define EPS 1e-5f

// -------- scratch (static device globals; no allocation) --------
__device__ float d_h[(size_t)N_NODES * D];      // hidden state between layers
__device__ float d_acc[(size_t)N_NODES * D];    // per-layer accumulator (pre-BN)
__device__ float d_neigh[(size_t)N_NODES * D];  // per-etype neighbor sum
__device__ float d_invdeg[NET * N_NODES];       // 1/clip(deg,1) per etype
__device__ float d_stats[2 * D];                // col sums / sumsq for BN

// ============================ utility kernels ============================

__global__ void zero_neigh_kernel() {
    size_t i = (size_t)blockIdx.x * blockDim.x + threadIdx.x;
    size_t n4 = (size_t)N_NODES * D / 4;
    if (i < n4) reinterpret_cast<float4*>(d_neigh)[i] = make_float4(0.f, 0.f, 0.f, 0.f);
}

__global__ void zero_deg_kernel() {
    int i = blockIdx.x * blockDim.x + threadIdx.x;
    if (i < NET * N_NODES) d_invdeg[i] = 0.f;
}

__global__ void zero_stats_kernel() {
    int i = threadIdx.x;
    if (i < 2 * D) d_stats[i] = 0.f;
}

__global__ void deg_count_kernel(const int* __restrict__ dst) {
    int idx = blockIdx.x * blockDim.x + threadIdx.x;
    if (idx >= NET * N_EDGES) return;
    int k = idx / N_EDGES;
    int d = __ldg(dst + idx);
    atomicAdd(&d_invdeg[k * N_NODES + d], 1.0f);
}

__global__ void deg_invert_kernel() {
    int i = blockIdx.x * blockDim.x + threadIdx.x;
    if (i < NET * N_NODES) d_invdeg[i] = 1.0f / fmaxf(d_invdeg[i], 1.0f);
}

// ============================ scatter (gather src rows, atomic-add to dst) ============================
// one warp per edge: 32 lanes x float4 = 128 floats
__global__ void scatter_kernel(const float* __restrict__ x, int use_x,
                               const int* __restrict__ src, const int* __restrict__ dst) {
    const float* hin = use_x ? x : d_h;
    int w = (blockIdx.x * blockDim.x + threadIdx.x) >> 5;
    int lane = threadIdx.x & 31;
    if (w >= N_EDGES) return;
    int s = __ldg(src + w);
    int d = __ldg(dst + w);
    float4 v = *reinterpret_cast<const float4*>(hin + (size_t)s * D + lane * 4);
    float* p = d_neigh + (size_t)d * D + lane * 4;
    asm volatile("red.global.add.v4.f32 [%0], {%1,%2,%3,%4};"
                 :: "l"(p), "f"(v.x), "f"(v.y), "f"(v.z), "f"(v.w)
                 : "memory");
}

// ============================ fused SGEMM ============================
// acc[ k==0 ? = : += ] relu?( [hin | neigh*invdeg] @ [Ws ; Wn] + bias )
// BM=128, BN=128(all), BK=16, 256 threads, 8x8 per thread
#define BM 128
#define BK 16

__global__ void __launch_bounds__(256, 2)
gemm_fused_kernel(const float* __restrict__ x, int use_x,
                  const float* __restrict__ Wself, const float* __restrict__ Wneigh,
                  const float* __restrict__ bias, int etype,
                  int accumulate, int do_relu) {
    const float* hin = use_x ? x : d_h;

    __shared__ float As[BK][BM + 4];
    __shared__ float Bs[BK][D];
    __shared__ float invd_s[BM];

    int tid = threadIdx.x;
    int m0 = blockIdx.x * BM;
    int tx = tid & 15;        // 0..15 -> cols
    int ty = tid >> 4;        // 0..15 -> rows

    if (tid < BM) {
        int r = m0 + tid;
        invd_s[tid] = (r < N_NODES) ? d_invdeg[etype * N_NODES + r] : 0.f;
    }

    float accr[8][8];
#pragma unroll
    for (int i = 0; i < 8; i++)
#pragma unroll
        for (int j = 0; j < 8; j++) accr[i][j] = 0.f;

    for (int kt = 0; kt < 2 * D; kt += BK) {
        bool neigh_phase = (kt >= D);
        int kk = neigh_phase ? (kt - D) : kt;

        __syncthreads();  // previous tile's compute done before overwrite

        // ---- load A tile (BM x BK), store transposed As[k][m] ----
#pragma unroll
        for (int j = 0; j < 2; j++) {
            int idx = tid * 2 + j;         // 0..511
            int row = idx >> 2;            // 0..127
            int c4 = (idx & 3) * 4;        // 0,4,8,12
            int gr = m0 + row;
            float4 v = make_float4(0.f, 0.f, 0.f, 0.f);
            if (gr < N_NODES) {
                const float* srcp = neigh_phase
                    ? (d_neigh + (size_t)gr * D + kk + c4)
                    : (hin + (size_t)gr * D + kk + c4);
                v = *reinterpret_cast<const float4*>(srcp);
                if (neigh_phase) {
                    float sc = invd_s[row];
                    v.x *= sc; v.y *= sc; v.z *= sc; v.w *= sc;
                }
            }
            As[c4 + 0][row] = v.x;
            As[c4 + 1][row] = v.y;
            As[c4 + 2][row] = v.z;
            As[c4 + 3][row] = v.w;
        }

        // ---- load B tile (BK x 128) ----
        const float* W = neigh_phase ? Wneigh : Wself;
#pragma unroll
        for (int j = 0; j < 2; j++) {
            int idx = tid * 2 + j;         // 0..511
            int row = idx >> 5;            // 0..15
            int c4 = (idx & 31) * 4;       // 0..124
            float4 v = *reinterpret_cast<const float4*>(W + (size_t)(kk + row) * D + c4);
            *reinterpret_cast<float4*>(&Bs[row][c4]) = v;
        }
        __syncthreads();

        // ---- compute ----
#pragma unroll
        for (int k = 0; k < BK; k++) {
            float a[8], bb[8];
#pragma unroll
            for (int i = 0; i < 8; i++) a[i] = As[k][ty * 8 + i];
#pragma unroll
            for (int j = 0; j < 8; j++) bb[j] = Bs[k][tx * 8 + j];
#pragma unroll
            for (int i = 0; i < 8; i++)
#pragma unroll
                for (int j = 0; j < 8; j++)
                    accr[i][j] = fmaf(a[i], bb[j], accr[i][j]);
        }
    }

    // ---- epilogue: bias, relu, accumulate into d_acc ----
#pragma unroll
    for (int i = 0; i < 8; i++) {
        int gm = m0 + ty * 8 + i;
        if (gm < N_NODES) {
#pragma unroll
            for (int j = 0; j < 8; j += 4) {
                int n = tx * 8 + j;
                float4 o;
                o.x = accr[i][j + 0] + __ldg(bias + n + 0);
                o.y = accr[i][j + 1] + __ldg(bias + n + 1);
                o.z = accr[i][j + 2] + __ldg(bias + n + 2);
                o.w = accr[i][j + 3] + __ldg(bias + n + 3);
                if (do_relu) {
                    o.x = fmaxf(o.x, 0.f); o.y = fmaxf(o.y, 0.f);
                    o.z = fmaxf(o.z, 0.f); o.w = fmaxf(o.w, 0.f);
                }
                float* p = d_acc + (size_t)gm * D + n;
                if (accumulate) {
                    float4 c = *reinterpret_cast<float4*>(p);
                    o.x += c.x; o.y += c.y; o.z += c.z; o.w += c.w;
                }
                *reinterpret_cast<float4*>(p) = o;
            }
        }
    }
}

// ============================ BatchNorm ============================

__global__ void bn_reduce_kernel() {
    int col = threadIdx.x;  // 128 threads
    int nblocks = gridDim.x;
    int rows_per = (N_NODES + nblocks - 1) / nblocks;
    int r0 = blockIdx.x * rows_per;
    int r1 = min(r0 + rows_per, N_NODES);
    float s = 0.f, sq = 0.f;
    for (int r = r0; r < r1; r++) {
        float v = d_acc[(size_t)r * D + col];
        s += v;
        sq = fmaf(v, v, sq);
    }
    atomicAdd(&d_stats[col], s);
    atomicAdd(&d_stats[D + col], sq);
}

__global__ void bn_norm_kernel(const float* __restrict__ gamma,
                               const float* __restrict__ beta,
                               float* __restrict__ outp, int write_out) {
    __shared__ float scale_s[D];
    __shared__ float shift_s[D];
    if (threadIdx.x < D) {
        int c = threadIdx.x;
        float mu = d_stats[c] * (1.0f / N_NODES);
        float var = d_stats[D + c] * (1.0f / N_NODES) - mu * mu;
        float sc = __ldg(gamma + c) * rsqrtf(var + EPS);
        scale_s[c] = sc;
        shift_s[c] = __ldg(beta + c) - mu * sc;
    }
    __syncthreads();
    float* dst = write_out ? outp : d_h;
    size_t i = (size_t)blockIdx.x * blockDim.x + threadIdx.x;
    size_t n4 = (size_t)N_NODES * D / 4;
    if (i >= n4) return;
    int col = (int)((i * 4) & (D - 1));
    float4 v = reinterpret_cast<const float4*>(d_acc)[i];
    float4 o;
    o.x = v.x * scale_s[col + 0] + shift_s[col + 0];
    o.y = v.y * scale_s[col + 1] + shift_s[col + 1];
    o.z = v.z * scale_s[col + 2] + shift_s[col + 2];
    o.w = v.w * scale_s[col + 3] + shift_s[col + 3];
    reinterpret_cast<float4*>(dst)[i] = o;
}

// ============================ launch ============================

extern "C" void kernel_launch(void* const* d_in, const int* in_sizes, int n_in,
                              void* d_out, int out_size) {
    const float* x     = (const float*)d_in[0];
    const int*   src   = (const int*)d_in[1];   // [3][600000]
    const int*   dst   = (const int*)d_in[2];   // [3][600000]
    const float* Ws    = (const float*)d_in[3]; // [3][3][128][128]
    const float* Wn    = (const float*)d_in[4]; // [3][3][128][128]
    const float* bias  = (const float*)d_in[5]; // [3][3][128]
    const float* gamma = (const float*)d_in[6]; // [3][128]
    const float* beta  = (const float*)d_in[7]; // [3][128]
    float* out = (float*)d_out;

    // ---- degrees (recomputed every call; deterministic work) ----
    {
        int n = NET * N_NODES;
        zero_deg_kernel<<<(n + 255) / 256, 256>>>();
        int ne = NET * N_EDGES;
        deg_count_kernel<<<(ne + 255) / 256, 256>>>(dst);
        deg_invert_kernel<<<(n + 255) / 256, 256>>>();
    }

    const int gemm_blocks = (N_NODES + BM - 1) / BM;            // 782
    const int neigh4 = N_NODES * D / 4;                         // 3.2M
    const int scatter_blocks = (N_EDGES * 32 + 255) / 256;      // 75000
    const int bn4_blocks = (N_NODES * D / 4 + 255) / 256;

    for (int l = 0; l < NL; l++) {
        int use_x = (l == 0);
        int do_relu = (l < NL - 1);
        for (int k = 0; k < NET; k++) {
            zero_neigh_kernel<<<(neigh4 + 255) / 256, 256>>>();
            scatter_kernel<<<scatter_blocks, 256>>>(x, use_x,
                                                    src + k * N_EDGES,
                                                    dst + k * N_EDGES);
            gemm_fused_kernel<<<gemm_blocks, 256>>>(
                x, use_x,
                Ws + (size_t)(l * NET + k) * D * D,
                Wn + (size_t)(l * NET + k) * D * D,
                bias + (size_t)(l * NET + k) * D,
                k, /*accumulate=*/(k > 0), do_relu);
        }
        zero_stats_kernel<<<1, 256>>>();
        bn_reduce_kernel<<<512, 128>>>();
        bn_norm_kernel<<<bn4_blocks, 256>>>(gamma + l * D, beta + l * D,
                                            out, /*write_out=*/(l == NL - 1));
    }
}

// round 5
// speedup vs baseline: 1.4078x; 1.3965x over previous
#include <cuda_runtime.h>
#include <cstdint>

#define NN 100000
#define NE 600000
#define NET 3
#define NL 3
#define DD 128
#define EPS 1e-5f

// ---------------- static device scratch (device-code access ONLY) ----------------
__device__ float d_h[(size_t)NN * DD];                 // hidden state
__device__ float d_neigh[(size_t)NET * NN * DD];       // per-etype neighbor means (pre-scaled)
__device__ float d_acc[(size_t)NN * DD];               // pre-BN accumulator
__device__ float d_invdeg[NET * NN];
__device__ float d_stats[2 * DD];
__device__ float d_Wr[(size_t)NL * NET * 2 * DD * DD]; // tf32-rounded weights [l][k][self/neigh][kk][n]

// ======================= prep kernels =======================

__global__ void zero_deg_kernel() {
    int i = blockIdx.x * blockDim.x + threadIdx.x;
    if (i < NET * NN) d_invdeg[i] = 0.f;
}
__global__ void deg_count_kernel(const int* __restrict__ dst) {
    int idx = blockIdx.x * blockDim.x + threadIdx.x;
    if (idx >= NET * NE) return;
    int k = idx / NE;
    atomicAdd(&d_invdeg[k * NN + __ldg(dst + idx)], 1.0f);
}
__global__ void deg_invert_kernel() {
    int i = blockIdx.x * blockDim.x + threadIdx.x;
    if (i < NET * NN) d_invdeg[i] = 1.0f / fmaxf(d_invdeg[i], 1.0f);
}

__device__ __forceinline__ uint32_t f2tf32(float x) {
    uint32_t r;
    asm("cvt.rna.tf32.f32 %0, %1;" : "=r"(r) : "f"(x));
    return r;
}

// elementwise tf32-round weights, layout preserved: [m][sel][kk][n]
__global__ void wr_prep_kernel(const float* __restrict__ Ws, const float* __restrict__ Wn) {
    int i = blockIdx.x * blockDim.x + threadIdx.x;
    if (i >= NL * NET * 2 * DD * DD) return;
    int sel = (i >> 14) & 1;
    int m = i >> 15;
    int off = i & 16383;
    float v = __ldg((sel ? Wn : Ws) + (size_t)m * 16384 + off);
    d_Wr[i] = __uint_as_float(f2tf32(v));
}

__global__ void zero_neigh_kernel() {
    int i = blockIdx.x * blockDim.x + threadIdx.x;
    if (i < NET * NN * 32) ((float4*)d_neigh)[i] = make_float4(0.f, 0.f, 0.f, 0.f);
}
__global__ void zero_stats_kernel() {
    int i = threadIdx.x;
    if (i < 2 * DD) d_stats[i] = 0.f;
}

// ======================= scatter (pre-scaled by 1/deg, batched over etypes) =======================
__global__ void scatter_kernel(const float* __restrict__ x, int use_x,
                               const int* __restrict__ src, const int* __restrict__ dst) {
    const float* hin = use_x ? x : d_h;
    int et = blockIdx.y;
    int w = (blockIdx.x * blockDim.x + threadIdx.x) >> 5;
    int lane = threadIdx.x & 31;
    if (w >= NE) return;
    int s = __ldg(src + (size_t)et * NE + w);
    int d = __ldg(dst + (size_t)et * NE + w);
    float sc = d_invdeg[et * NN + d];
    float4 v = *reinterpret_cast<const float4*>(hin + (size_t)s * DD + lane * 4);
    v.x *= sc; v.y *= sc; v.z *= sc; v.w *= sc;
    float* p = d_neigh + ((size_t)et * NN + d) * DD + lane * 4;
    asm volatile("red.global.add.v4.f32 [%0], {%1,%2,%3,%4};"
                 :: "l"(p), "f"(v.x), "f"(v.y), "f"(v.z), "f"(v.w) : "memory");
}

// ======================= tf32 mma.sync fused GEMM =======================
// d_acc [= or +=] relu?( [hin | neigh_k] @ [Ws ; Wn] + bias ), M-tile 128, N=128, K=256
// 256 threads = 8 warps in 4(m) x 2(n); warp tile 32x64; fragments m16n8k8

#define BK 32
#define ASTRIDE 36
#define BSTRIDE 136
#define ASZ (128 * ASTRIDE)
#define BSZ (BK * BSTRIDE)
#define SMEM_BYTES (2 * (ASZ + BSZ) * 4)

__device__ __forceinline__ void ldA(float4* ra, const float* __restrict__ A,
                                    int m0, int kk, int tid) {
#pragma unroll
    for (int t = 0; t < 4; t++) {
        int c = tid + t * 256;
        int row = c >> 3;
        int gr = m0 + row;
        ra[t] = (gr < NN)
            ? __ldg(reinterpret_cast<const float4*>(A + (size_t)gr * DD + kk) + (c & 7))
            : make_float4(0.f, 0.f, 0.f, 0.f);
    }
}
__device__ __forceinline__ void ldB(float4* rb, const float* __restrict__ W,
                                    int kk, int tid) {
#pragma unroll
    for (int t = 0; t < 4; t++) {
        int c = tid + t * 256;
        int row = c >> 5;
        rb[t] = __ldg(reinterpret_cast<const float4*>(W + (size_t)(kk + row) * DD) + (c & 31));
    }
}
__device__ __forceinline__ void stsA(float* As, const float4* ra, int tid) {
#pragma unroll
    for (int t = 0; t < 4; t++) {
        int c = tid + t * 256;
        int row = c >> 3, col = (c & 7) << 2;
        uint4 u;
        u.x = f2tf32(ra[t].x); u.y = f2tf32(ra[t].y);
        u.z = f2tf32(ra[t].z); u.w = f2tf32(ra[t].w);
        *reinterpret_cast<uint4*>(As + row * ASTRIDE + col) = u;
    }
}
__device__ __forceinline__ void stsB(float* Bs, const float4* rb, int tid) {
#pragma unroll
    for (int t = 0; t < 4; t++) {
        int c = tid + t * 256;
        int row = c >> 5, col = (c & 31) << 2;
        *reinterpret_cast<float4*>(Bs + row * BSTRIDE + col) = rb[t];  // pre-rounded
    }
}

__device__ __forceinline__ void mma8(float* c, uint32_t a0, uint32_t a1, uint32_t a2, uint32_t a3,
                                     uint32_t b0, uint32_t b1) {
    asm volatile("mma.sync.aligned.m16n8k8.row.col.f32.tf32.tf32.f32 "
                 "{%0,%1,%2,%3}, {%4,%5,%6,%7}, {%8,%9}, {%0,%1,%2,%3};"
                 : "+f"(c[0]), "+f"(c[1]), "+f"(c[2]), "+f"(c[3])
                 : "r"(a0), "r"(a1), "r"(a2), "r"(a3), "r"(b0), "r"(b1));
}

__device__ __forceinline__ void tile_compute(const float* __restrict__ As,
                                             const float* __restrict__ Bs,
                                             float acc[2][8][4], int lane, int wm, int wn) {
#pragma unroll
    for (int ks = 0; ks < 4; ks++) {
        uint32_t af[2][4];
#pragma unroll
        for (int mf = 0; mf < 2; mf++) {
            const float* p = As + (wm * 32 + mf * 16 + (lane >> 2)) * ASTRIDE + ks * 8 + (lane & 3);
            af[mf][0] = __float_as_uint(p[0]);
            af[mf][1] = __float_as_uint(p[8 * ASTRIDE]);
            af[mf][2] = __float_as_uint(p[4]);
            af[mf][3] = __float_as_uint(p[8 * ASTRIDE + 4]);
        }
        uint32_t bf[8][2];
#pragma unroll
        for (int nf = 0; nf < 8; nf++) {
            const float* q = Bs + (ks * 8 + (lane & 3)) * BSTRIDE + wn * 64 + nf * 8 + (lane >> 2);
            bf[nf][0] = __float_as_uint(q[0]);
            bf[nf][1] = __float_as_uint(q[4 * BSTRIDE]);
        }
#pragma unroll
        for (int mf = 0; mf < 2; mf++)
#pragma unroll
            for (int nf = 0; nf < 8; nf++)
                mma8(acc[mf][nf], af[mf][0], af[mf][1], af[mf][2], af[mf][3],
                     bf[nf][0], bf[nf][1]);
    }
}

__global__ void __launch_bounds__(256)
gemm_mma_kernel(const float* __restrict__ x, int use_x, int etype, int widx,
                const float* __restrict__ bias, int accumulate, int do_relu) {
    extern __shared__ float sm[];
    float* As0 = sm;
    float* Bs0 = sm + ASZ;
    float* As1 = sm + ASZ + BSZ;
    float* Bs1 = sm + 2 * ASZ + BSZ;

    // device-side pointer derivation (NEVER pass __device__ symbols from host!)
    const float* hin    = use_x ? x : d_h;
    const float* neigh  = d_neigh + (size_t)etype * NN * DD;
    const float* Wself  = d_Wr + (size_t)(widx * 2) * DD * DD;
    const float* Wneigh = Wself + DD * DD;

    int tid = threadIdx.x, lane = tid & 31, wid = tid >> 5;
    int wm = wid & 3, wn = wid >> 2;
    int m0 = blockIdx.x * 128;

    float acc[2][8][4];
#pragma unroll
    for (int i = 0; i < 2; i++)
#pragma unroll
        for (int j = 0; j < 8; j++)
#pragma unroll
            for (int e = 0; e < 4; e++) acc[i][j][e] = 0.f;

    float4 ra[4], rb[4];
    ldA(ra, hin, m0, 0, tid);
    ldB(rb, Wself, 0, tid);
    stsA(As0, ra, tid);
    stsB(Bs0, rb, tid);
    __syncthreads();

#pragma unroll
    for (int kt = 0; kt < 8; kt++) {
        const float* Ab = (kt & 1) ? As1 : As0;
        const float* Bb = (kt & 1) ? Bs1 : Bs0;
        if (kt < 7) {
            int nk = kt + 1;
            ldA(ra, (nk < 4) ? hin : neigh, m0, (nk & 3) * 32, tid);
            ldB(rb, (nk < 4) ? Wself : Wneigh, (nk & 3) * 32, tid);
        }
        tile_compute(Ab, Bb, acc, lane, wm, wn);
        if (kt < 7) {
            __syncthreads();
            stsA((kt & 1) ? As0 : As1, ra, tid);
            stsB((kt & 1) ? Bs0 : Bs1, rb, tid);
            __syncthreads();
        }
    }

    // ---- epilogue ----
#pragma unroll
    for (int mf = 0; mf < 2; mf++) {
        int r0 = m0 + wm * 32 + mf * 16 + (lane >> 2);
#pragma unroll
        for (int nf = 0; nf < 8; nf++) {
            int n = wn * 64 + nf * 8 + ((lane & 3) << 1);
            float b0 = __ldg(bias + n), b1 = __ldg(bias + n + 1);
            float v0 = acc[mf][nf][0] + b0, v1 = acc[mf][nf][1] + b1;
            float v2 = acc[mf][nf][2] + b0, v3 = acc[mf][nf][3] + b1;
            if (do_relu) {
                v0 = fmaxf(v0, 0.f); v1 = fmaxf(v1, 0.f);
                v2 = fmaxf(v2, 0.f); v3 = fmaxf(v3, 0.f);
            }
            if (r0 < NN) {
                float2* p = reinterpret_cast<float2*>(d_acc + (size_t)r0 * DD + n);
                float2 o = make_float2(v0, v1);
                if (accumulate) { float2 c = *p; o.x += c.x; o.y += c.y; }
                *p = o;
            }
            if (r0 + 8 < NN) {
                float2* p = reinterpret_cast<float2*>(d_acc + (size_t)(r0 + 8) * DD + n);
                float2 o = make_float2(v2, v3);
                if (accumulate) { float2 c = *p; o.x += c.x; o.y += c.y; }
                *p = o;
            }
        }
    }
}

// ======================= BatchNorm =======================

__global__ void bn_reduce_kernel() {
    int col = threadIdx.x;
    int rows_per = (NN + gridDim.x - 1) / gridDim.x;
    int r0 = blockIdx.x * rows_per;
    int r1 = min(r0 + rows_per, NN);
    float s = 0.f, sq = 0.f;
    for (int r = r0; r < r1; r++) {
        float v = d_acc[(size_t)r * DD + col];
        s += v;
        sq = fmaf(v, v, sq);
    }
    atomicAdd(&d_stats[col], s);
    atomicAdd(&d_stats[DD + col], sq);
}

__global__ void bn_norm_kernel(const float* __restrict__ gamma,
                               const float* __restrict__ beta,
                               float* __restrict__ outp, int write_out) {
    __shared__ float scale_s[DD];
    __shared__ float shift_s[DD];
    if (threadIdx.x < DD) {
        int c = threadIdx.x;
        float mu = d_stats[c] * (1.0f / NN);
        float var = d_stats[DD + c] * (1.0f / NN) - mu * mu;
        float sc = __ldg(gamma + c) * rsqrtf(var + EPS);
        scale_s[c] = sc;
        shift_s[c] = __ldg(beta + c) - mu * sc;
    }
    __syncthreads();
    float* dstp = write_out ? outp : d_h;
    size_t i = (size_t)blockIdx.x * blockDim.x + threadIdx.x;
    if (i >= (size_t)NN * DD / 4) return;
    int col = (int)((i * 4) & (DD - 1));
    float4 v = reinterpret_cast<const float4*>(d_acc)[i];
    float4 o;
    o.x = v.x * scale_s[col + 0] + shift_s[col + 0];
    o.y = v.y * scale_s[col + 1] + shift_s[col + 1];
    o.z = v.z * scale_s[col + 2] + shift_s[col + 2];
    o.w = v.w * scale_s[col + 3] + shift_s[col + 3];
    reinterpret_cast<float4*>(dstp)[i] = o;
}

// ======================= launch =======================

extern "C" void kernel_launch(void* const* d_in, const int* in_sizes, int n_in,
                              void* d_out, int out_size) {
    const float* x     = (const float*)d_in[0];
    const int*   src   = (const int*)d_in[1];
    const int*   dst   = (const int*)d_in[2];
    const float* Ws    = (const float*)d_in[3];
    const float* Wn    = (const float*)d_in[4];
    const float* bias  = (const float*)d_in[5];
    const float* gamma = (const float*)d_in[6];
    const float* beta  = (const float*)d_in[7];
    float* out = (float*)d_out;

    cudaFuncSetAttribute(gemm_mma_kernel,
                         cudaFuncAttributeMaxDynamicSharedMemorySize, SMEM_BYTES);

    // weight tf32 rounding
    {
        int n = NL * NET * 2 * DD * DD;
        wr_prep_kernel<<<(n + 255) / 256, 256>>>(Ws, Wn);
    }
    // degrees
    {
        int n = NET * NN;
        zero_deg_kernel<<<(n + 255) / 256, 256>>>();
        int ne = NET * NE;
        deg_count_kernel<<<(ne + 255) / 256, 256>>>(dst);
        deg_invert_kernel<<<(n + 255) / 256, 256>>>();
    }

    const int gemm_blocks = (NN + 127) / 128;  // 782
    const int zero_blocks = (NET * NN * 32 + 255) / 256;
    const dim3 scatter_grid((NE * 32 + 255) / 256, NET);
    const int bn4_blocks = (NN * DD / 4 + 255) / 256;

    for (int l = 0; l < NL; l++) {
        int use_x = (l == 0);
        int do_relu = (l < NL - 1);
        zero_neigh_kernel<<<zero_blocks, 256>>>();
        scatter_kernel<<<scatter_grid, 256>>>(x, use_x, src, dst);
        for (int k = 0; k < NET; k++) {
            gemm_mma_kernel<<<gemm_blocks, 256, SMEM_BYTES>>>(
                x, use_x, k, l * NET + k,
                bias + (size_t)(l * NET + k) * DD,
                /*accumulate=*/(k > 0), do_relu);
        }
        zero_stats_kernel<<<1, 256>>>();
        bn_reduce_kernel<<<512, 128>>>();
        bn_norm_kernel<<<bn4_blocks, 256>>>(gamma + l * DD, beta + l * DD,
                                            out, (l == NL - 1));
    }
}

// round 6
// speedup vs baseline: 1.7947x; 1.2748x over previous
#include <cuda_runtime.h>
#include <cstdint>

#define NN 100000
#define NE 600000
#define NET 3
#define NL 3
#define DD 128
#define EPS 1e-5f

// ---------------- static device scratch (device-code access ONLY) ----------------
__device__ float d_h[(size_t)NN * DD];
__device__ float d_neigh[(size_t)NET * NN * DD];
__device__ float d_acc[(size_t)NN * DD];
__device__ float d_invdeg[NET * NN];
__device__ float d_stats3[NL * 2 * DD];                 // per-layer BN sums/sumsq
__device__ float d_Wt[(size_t)NL * NET * 2 * DD * DD];  // W^T tf32: [l][e][sel][n][kk]

// ======================= prep kernels =======================

__global__ void zero_deg_kernel() {
    int i = blockIdx.x * blockDim.x + threadIdx.x;
    if (i < NET * NN) d_invdeg[i] = 0.f;
    if (i < NL * 2 * DD) d_stats3[i] = 0.f;
}
__global__ void deg_count_kernel(const int* __restrict__ dst) {
    int idx = blockIdx.x * blockDim.x + threadIdx.x;
    if (idx >= NET * NE) return;
    int k = idx / NE;
    atomicAdd(&d_invdeg[k * NN + __ldg(dst + idx)], 1.0f);
}
__global__ void deg_invert_kernel() {
    int i = blockIdx.x * blockDim.x + threadIdx.x;
    if (i < NET * NN) d_invdeg[i] = 1.0f / fmaxf(d_invdeg[i], 1.0f);
}

__device__ __forceinline__ uint32_t f2tf32(float x) {
    uint32_t r;
    asm("cvt.rna.tf32.f32 %0, %1;" : "=r"(r) : "f"(x));
    return r;
}

// transpose + tf32 round: d_Wt[(m*2+sel)*16384 + n*128 + kk] = tf32(W[m][sel][kk][n])
__global__ void wt_prep_kernel(const float* __restrict__ Ws, const float* __restrict__ Wn) {
    int i = blockIdx.x * blockDim.x + threadIdx.x;
    if (i >= NL * NET * 2 * DD * DD) return;
    int kk = i & 127;
    int n = (i >> 7) & 127;
    int sel = (i >> 14) & 1;
    int m = i >> 15;
    float v = __ldg((sel ? Wn : Ws) + (size_t)m * 16384 + kk * DD + n);
    d_Wt[i] = __uint_as_float(f2tf32(v));
}

__global__ void zero_neigh_kernel() {
    int i = blockIdx.x * blockDim.x + threadIdx.x;
    if (i < NET * NN * 32) ((float4*)d_neigh)[i] = make_float4(0.f, 0.f, 0.f, 0.f);
}

// ======================= scatter (pre-scaled by 1/deg) =======================
__global__ void scatter_kernel(const float* __restrict__ x, int use_x,
                               const int* __restrict__ src, const int* __restrict__ dst) {
    const float* hin = use_x ? x : d_h;
    int et = blockIdx.y;
    int w = (blockIdx.x * blockDim.x + threadIdx.x) >> 5;
    int lane = threadIdx.x & 31;
    if (w >= NE) return;
    int s = __ldg(src + (size_t)et * NE + w);
    int d = __ldg(dst + (size_t)et * NE + w);
    float sc = d_invdeg[et * NN + d];
    float4 v = *reinterpret_cast<const float4*>(hin + (size_t)s * DD + lane * 4);
    v.x *= sc; v.y *= sc; v.z *= sc; v.w *= sc;
    float* p = d_neigh + ((size_t)et * NN + d) * DD + lane * 4;
    asm volatile("red.global.add.v4.f32 [%0], {%1,%2,%3,%4};"
                 :: "l"(p), "f"(v.x), "f"(v.y), "f"(v.z), "f"(v.w) : "memory");
}

// ======================= merged tf32 mma GEMM (all 3 etypes, fused BN-reduce) =======================
// acc = sum_e relu?( [hin | neigh_e] @ [Ws_e ; Wn_e] + b_e );  also accumulates BN col stats.
// 256 thr = 8 warps 4(m)x2(n); warp tile 32x64; m16n8k8 tf32; ldmatrix fragment loads.

#define ASTRIDE 36
#define ATILE (128 * ASTRIDE)
#define SMEM_BYTES (4 * ATILE * 4)   // As0,As1,Bs0,Bs1 = 73728 B

__device__ __forceinline__ void ldsm4(uint32_t* r, uint32_t addr) {
    asm volatile("ldmatrix.sync.aligned.m8n8.x4.shared.b16 {%0,%1,%2,%3}, [%4];"
                 : "=r"(r[0]), "=r"(r[1]), "=r"(r[2]), "=r"(r[3]) : "r"(addr));
}
__device__ __forceinline__ void mma8(float* c, const uint32_t* a, uint32_t b0, uint32_t b1) {
    asm volatile("mma.sync.aligned.m16n8k8.row.col.f32.tf32.tf32.f32 "
                 "{%0,%1,%2,%3}, {%4,%5,%6,%7}, {%8,%9}, {%0,%1,%2,%3};"
                 : "+f"(c[0]), "+f"(c[1]), "+f"(c[2]), "+f"(c[3])
                 : "r"(a[0]), "r"(a[1]), "r"(a[2]), "r"(a[3]), "r"(b0), "r"(b1));
}

__device__ __forceinline__ void ldgA(float4* ra, const float* __restrict__ src,
                                     int m0, int koff, int tid) {
#pragma unroll
    for (int t = 0; t < 4; t++) {
        int c = tid + t * 256;
        int gr = m0 + (c >> 3);
        ra[t] = (gr < NN)
            ? __ldg(reinterpret_cast<const float4*>(src + (size_t)gr * DD + koff) + (c & 7))
            : make_float4(0.f, 0.f, 0.f, 0.f);
    }
}
__device__ __forceinline__ void ldgB(float4* rb, const float* __restrict__ W,
                                     int koff, int tid) {
#pragma unroll
    for (int t = 0; t < 4; t++) {
        int c = tid + t * 256;
        rb[t] = __ldg(reinterpret_cast<const float4*>(W + (size_t)(c >> 3) * DD + koff) + (c & 7));
    }
}
__device__ __forceinline__ void stsA(float* As, const float4* ra, int tid) {
#pragma unroll
    for (int t = 0; t < 4; t++) {
        int c = tid + t * 256;
        uint4 u;
        u.x = f2tf32(ra[t].x); u.y = f2tf32(ra[t].y);
        u.z = f2tf32(ra[t].z); u.w = f2tf32(ra[t].w);
        *reinterpret_cast<uint4*>(As + (c >> 3) * ASTRIDE + (c & 7) * 4) = u;
    }
}
__device__ __forceinline__ void stsB(float* Bs, const float4* rb, int tid) {
#pragma unroll
    for (int t = 0; t < 4; t++) {
        int c = tid + t * 256;
        *reinterpret_cast<float4*>(Bs + (c >> 3) * ASTRIDE + (c & 7) * 4) = rb[t];
    }
}

__global__ void __launch_bounds__(256)
gemm_merged_kernel(const float* __restrict__ x, int use_x, int layer,
                   const float* __restrict__ bias /*[NET][128]*/, int do_relu) {
    extern __shared__ float sm[];
    float* Abuf[2] = { sm, sm + ATILE };
    float* Bbuf[2] = { sm + 2 * ATILE, sm + 3 * ATILE };
    uint32_t smb = (uint32_t)__cvta_generic_to_shared(sm);
    uint32_t asu[2] = { smb, smb + ATILE * 4 };
    uint32_t bsu[2] = { smb + 2 * ATILE * 4, smb + 3 * ATILE * 4 };

    const float* hin = use_x ? x : d_h;
    const float* Wl = d_Wt + (size_t)layer * NET * 2 * DD * DD;
    float* stats = d_stats3 + layer * 2 * DD;

    int tid = threadIdx.x, lane = tid & 31, wid = tid >> 5;
    int wm = wid & 3, wn = wid >> 2;
    int m0 = blockIdx.x * 128;

    // ldmatrix per-lane byte offsets
    uint32_t aoffb[2];
#pragma unroll
    for (int mf = 0; mf < 2; mf++)
        aoffb[mf] = ((wm * 32 + mf * 16 + (lane & 15)) * ASTRIDE + (lane >> 4) * 4) * 4;
    uint32_t boffb[4];
#pragma unroll
    for (int nf2 = 0; nf2 < 4; nf2++) {
        int n = wn * 64 + nf2 * 16 + (lane & 7) + ((lane >> 4) << 3);
        boffb[nf2] = (n * ASTRIDE + ((lane >> 3) & 1) * 4) * 4;
    }

    float facc[2][8][4], acc[2][8][4];
#pragma unroll
    for (int i = 0; i < 2; i++)
#pragma unroll
        for (int j = 0; j < 8; j++)
#pragma unroll
            for (int e = 0; e < 4; e++) { facc[i][j][e] = 0.f; acc[i][j][e] = 0.f; }

    float4 ra[4], rb[4];
    ldgA(ra, hin, m0, 0, tid);
    ldgB(rb, Wl, 0, tid);
    stsA(Abuf[0], ra, tid);
    stsB(Bbuf[0], rb, tid);
    __syncthreads();

#pragma unroll
    for (int t = 0; t < 24; t++) {
        const int cur = t & 1;
        if (t < 23) {
            const int tn = t + 1, pn = tn >> 2;
            const float* Asrc = (pn & 1) ? (d_neigh + (size_t)(pn >> 1) * NN * DD) : hin;
            ldgA(ra, Asrc, m0, (tn & 3) * 32, tid);
            ldgB(rb, Wl + (size_t)pn * DD * DD, (tn & 3) * 32, tid);
        }
        // ---- compute tile t from buffer cur ----
#pragma unroll
        for (int ks = 0; ks < 4; ks++) {
            uint32_t af[2][4];
            ldsm4(af[0], asu[cur] + aoffb[0] + ks * 32);
            ldsm4(af[1], asu[cur] + aoffb[1] + ks * 32);
            uint32_t bf[4][4];
#pragma unroll
            for (int nf2 = 0; nf2 < 4; nf2++)
                ldsm4(bf[nf2], bsu[cur] + boffb[nf2] + ks * 32);
#pragma unroll
            for (int mf = 0; mf < 2; mf++)
#pragma unroll
                for (int nf = 0; nf < 8; nf++) {
                    int q = (nf & 1) * 2;
                    mma8(acc[mf][nf], af[mf], bf[nf >> 1][q], bf[nf >> 1][q + 1]);
                }
        }
        // ---- etype boundary: bias + relu, fold into facc ----
        if (t == 7 || t == 15 || t == 23) {
            const float* be = bias + (t >> 3) * DD;
#pragma unroll
            for (int nf = 0; nf < 8; nf++) {
                int n = wn * 64 + nf * 8 + ((lane & 3) << 1);
                float b0 = __ldg(be + n), b1 = __ldg(be + n + 1);
#pragma unroll
                for (int mf = 0; mf < 2; mf++) {
                    float v0 = acc[mf][nf][0] + b0, v1 = acc[mf][nf][1] + b1;
                    float v2 = acc[mf][nf][2] + b0, v3 = acc[mf][nf][3] + b1;
                    if (do_relu) {
                        v0 = fmaxf(v0, 0.f); v1 = fmaxf(v1, 0.f);
                        v2 = fmaxf(v2, 0.f); v3 = fmaxf(v3, 0.f);
                    }
                    facc[mf][nf][0] += v0; facc[mf][nf][1] += v1;
                    facc[mf][nf][2] += v2; facc[mf][nf][3] += v3;
                    acc[mf][nf][0] = 0.f; acc[mf][nf][1] = 0.f;
                    acc[mf][nf][2] = 0.f; acc[mf][nf][3] = 0.f;
                }
            }
        }
        if (t < 23) {
            __syncthreads();
            stsA(Abuf[1 - cur], ra, tid);
            stsB(Bbuf[1 - cur], rb, tid);
            __syncthreads();
        }
    }

    // ---- epilogue: store + fused BN column stats ----
    int r0 = m0 + wm * 32 + (lane >> 2);
    int rr[2] = { r0, r0 + 16 };
#pragma unroll
    for (int nf = 0; nf < 8; nf++) {
        int n = wn * 64 + nf * 8 + ((lane & 3) << 1);
        float s0 = 0.f, s1 = 0.f, q0 = 0.f, q1 = 0.f;
#pragma unroll
        for (int mf = 0; mf < 2; mf++) {
            int r = rr[mf];
            float v0 = facc[mf][nf][0], v1 = facc[mf][nf][1];
            float v2 = facc[mf][nf][2], v3 = facc[mf][nf][3];
            if (r < NN) {
                *reinterpret_cast<float2*>(d_acc + (size_t)r * DD + n) = make_float2(v0, v1);
                s0 += v0; s1 += v1;
                q0 = fmaf(v0, v0, q0); q1 = fmaf(v1, v1, q1);
            }
            if (r + 8 < NN) {
                *reinterpret_cast<float2*>(d_acc + (size_t)(r + 8) * DD + n) = make_float2(v2, v3);
                s0 += v2; s1 += v3;
                q0 = fmaf(v2, v2, q0); q1 = fmaf(v3, v3, q1);
            }
        }
#pragma unroll
        for (int o = 4; o < 32; o <<= 1) {
            s0 += __shfl_xor_sync(0xFFFFFFFFu, s0, o);
            s1 += __shfl_xor_sync(0xFFFFFFFFu, s1, o);
            q0 += __shfl_xor_sync(0xFFFFFFFFu, q0, o);
            q1 += __shfl_xor_sync(0xFFFFFFFFu, q1, o);
        }
        if (lane < 4) {
            atomicAdd(stats + n, s0);
            atomicAdd(stats + n + 1, s1);
            atomicAdd(stats + DD + n, q0);
            atomicAdd(stats + DD + n + 1, q1);
        }
    }
}

// ======================= BatchNorm normalize =======================

__global__ void bn_norm_kernel(const float* __restrict__ gamma,
                               const float* __restrict__ beta,
                               float* __restrict__ outp, int write_out, int layer) {
    __shared__ float scale_s[DD];
    __shared__ float shift_s[DD];
    if (threadIdx.x < DD) {
        int c = threadIdx.x;
        const float* stats = d_stats3 + layer * 2 * DD;
        float mu = stats[c] * (1.0f / NN);
        float var = stats[DD + c] * (1.0f / NN) - mu * mu;
        float sc = __ldg(gamma + c) * rsqrtf(var + EPS);
        scale_s[c] = sc;
        shift_s[c] = __ldg(beta + c) - mu * sc;
    }
    __syncthreads();
    float* dstp = write_out ? outp : d_h;
    size_t i = (size_t)blockIdx.x * blockDim.x + threadIdx.x;
    if (i >= (size_t)NN * DD / 4) return;
    int col = (int)((i * 4) & (DD - 1));
    float4 v = reinterpret_cast<const float4*>(d_acc)[i];
    float4 o;
    o.x = v.x * scale_s[col + 0] + shift_s[col + 0];
    o.y = v.y * scale_s[col + 1] + shift_s[col + 1];
    o.z = v.z * scale_s[col + 2] + shift_s[col + 2];
    o.w = v.w * scale_s[col + 3] + shift_s[col + 3];
    reinterpret_cast<float4*>(dstp)[i] = o;
}

// ======================= launch =======================

extern "C" void kernel_launch(void* const* d_in, const int* in_sizes, int n_in,
                              void* d_out, int out_size) {
    const float* x     = (const float*)d_in[0];
    const int*   src   = (const int*)d_in[1];
    const int*   dst   = (const int*)d_in[2];
    const float* Ws    = (const float*)d_in[3];
    const float* Wn    = (const float*)d_in[4];
    const float* bias  = (const float*)d_in[5];
    const float* gamma = (const float*)d_in[6];
    const float* beta  = (const float*)d_in[7];
    float* out = (float*)d_out;

    cudaFuncSetAttribute(gemm_merged_kernel,
                         cudaFuncAttributeMaxDynamicSharedMemorySize, SMEM_BYTES);

    {
        int n = NL * NET * 2 * DD * DD;
        wt_prep_kernel<<<(n + 255) / 256, 256>>>(Ws, Wn);
    }
    {
        int n = NET * NN;
        zero_deg_kernel<<<(n + 255) / 256, 256>>>();
        int ne = NET * NE;
        deg_count_kernel<<<(ne + 255) / 256, 256>>>(dst);
        deg_invert_kernel<<<(n + 255) / 256, 256>>>();
    }

    const int gemm_blocks = (NN + 127) / 128;  // 782
    const int zero_blocks = (NET * NN * 32 + 255) / 256;
    const dim3 scatter_grid((NE * 32 + 255) / 256, NET);
    const int bn4_blocks = (NN * DD / 4 + 255) / 256;

    for (int l = 0; l < NL; l++) {
        int use_x = (l == 0);
        int do_relu = (l < NL - 1);
        zero_neigh_kernel<<<zero_blocks, 256>>>();
        scatter_kernel<<<scatter_grid, 256>>>(x, use_x, src, dst);
        gemm_merged_kernel<<<gemm_blocks, 256, SMEM_BYTES>>>(
            x, use_x, l, bias + (size_t)l * NET * DD, do_relu);
        bn_norm_kernel<<<bn4_blocks, 256>>>(gamma + l * DD, beta + l * DD,
                                            out, (l == NL - 1), l);
    }
}

// round 7
// speedup vs baseline: 2.6942x; 1.5012x over previous
#include <cuda_runtime.h>
#include <cstdint>

#define NN 100000
#define NE 600000
#define NET 3
#define NL 3
#define DD 128
#define EPS 1e-5f
#define NROWS (NET * NN)          // 300000
#define SCAN_BLK 293              // ceil(300000/1024)

// ---------------- static device scratch (device-code access ONLY) ----------------
__device__ float d_h[(size_t)NN * DD];
__device__ float d_neigh[(size_t)NET * NN * DD];
__device__ float d_acc[(size_t)NN * DD];
__device__ float d_invdeg[NROWS];
__device__ float d_stats3[NL * 2 * DD];
__device__ float d_Wt[(size_t)NL * NET * 2 * DD * DD];  // W^T tf32: [l][e][sel][n][kk]
__device__ int   d_cnt[NROWS];
__device__ int   d_rowoff[NROWS + 1];
__device__ int   d_bsums[512];
__device__ int   d_esrc[NET * NE];

// ======================= prep: degrees + CSR =======================

__global__ void zero_cnt_kernel() {
    int i = blockIdx.x * blockDim.x + threadIdx.x;
    if (i < NROWS) d_cnt[i] = 0;
    if (i < NL * 2 * DD) d_stats3[i] = 0.f;
}
__global__ void deg_count_kernel(const int* __restrict__ dst) {
    int idx = blockIdx.x * blockDim.x + threadIdx.x;
    if (idx >= NET * NE) return;
    int k = idx / NE;
    atomicAdd(&d_cnt[k * NN + __ldg(dst + idx)], 1);
}

// scan stage 1: per-1024-chunk sums
__global__ void scan1_kernel() {
    int base = blockIdx.x * 1024;
    int t = threadIdx.x;
    int sum = 0;
#pragma unroll
    for (int j = 0; j < 4; j++) {
        int i = base + t * 4 + j;
        if (i < NROWS) sum += d_cnt[i];
    }
#pragma unroll
    for (int o = 16; o; o >>= 1) sum += __shfl_down_sync(0xFFFFFFFFu, sum, o);
    __shared__ int ws[8];
    if ((t & 31) == 0) ws[t >> 5] = sum;
    __syncthreads();
    if (t == 0) {
        int v = 0;
#pragma unroll
        for (int i = 0; i < 8; i++) v += ws[i];
        d_bsums[blockIdx.x] = v;
    }
}

// scan stage 2: exclusive scan of block sums (single block, 512 threads)
__global__ void scan2_kernel() {
    __shared__ int s[512];
    int t = threadIdx.x;
    int orig = (t < SCAN_BLK) ? d_bsums[t] : 0;
    s[t] = orig;
    __syncthreads();
#pragma unroll
    for (int o = 1; o < 512; o <<= 1) {
        int v = (t >= o) ? s[t - o] : 0;
        __syncthreads();
        s[t] += v;
        __syncthreads();
    }
    if (t < SCAN_BLK) d_bsums[t] = s[t] - orig;  // exclusive
}

// scan stage 3: intra-block exclusive scan + write rowoff, invdeg; zero cnt for permute
__global__ void scan3_kernel() {
    int base = blockIdx.x * 1024;
    int t = threadIdx.x, lane = t & 31, warp = t >> 5;
    int vals[4];
    int tsum = 0;
#pragma unroll
    for (int j = 0; j < 4; j++) {
        int i = base + t * 4 + j;
        vals[j] = (i < NROWS) ? d_cnt[i] : 0;
        tsum += vals[j];
    }
    // warp inclusive scan of tsum
    int inc = tsum;
#pragma unroll
    for (int o = 1; o < 32; o <<= 1) {
        int v = __shfl_up_sync(0xFFFFFFFFu, inc, o);
        if (lane >= o) inc += v;
    }
    int texcl = inc - tsum;
    __shared__ int wsum[8];
    if (lane == 31) wsum[warp] = inc;
    __syncthreads();
    __shared__ int woff[8];
    if (t == 0) {
        int a = 0;
#pragma unroll
        for (int i = 0; i < 8; i++) { woff[i] = a; a += wsum[i]; }
    }
    __syncthreads();
    int run = d_bsums[blockIdx.x] + woff[warp] + texcl;
#pragma unroll
    for (int j = 0; j < 4; j++) {
        int i = base + t * 4 + j;
        if (i < NROWS) {
            d_rowoff[i] = run;
            d_invdeg[i] = 1.0f / fmaxf((float)vals[j], 1.0f);
            d_cnt[i] = 0;
            run += vals[j];
        }
    }
    if (blockIdx.x == 0 && t == 0) d_rowoff[NROWS] = NET * NE;
}

// permute edges into dst-grouped order
__global__ void permute_kernel(const int* __restrict__ src, const int* __restrict__ dst) {
    int idx = blockIdx.x * blockDim.x + threadIdx.x;
    if (idx >= NET * NE) return;
    int k = idx / NE;
    int g = k * NN + __ldg(dst + idx);
    int pos = d_rowoff[g] + atomicAdd(&d_cnt[g], 1);
    d_esrc[pos] = __ldg(src + idx);
}

__device__ __forceinline__ uint32_t f2tf32(float x) {
    uint32_t r;
    asm("cvt.rna.tf32.f32 %0, %1;" : "=r"(r) : "f"(x));
    return r;
}

// transpose + tf32 round: d_Wt[(m*2+sel)*16384 + n*128 + kk] = tf32(W[m][sel][kk][n])
__global__ void wt_prep_kernel(const float* __restrict__ Ws, const float* __restrict__ Wn) {
    int i = blockIdx.x * blockDim.x + threadIdx.x;
    if (i >= NL * NET * 2 * DD * DD) return;
    int kk = i & 127;
    int n = (i >> 7) & 127;
    int sel = (i >> 14) & 1;
    int m = i >> 15;
    float v = __ldg((sel ? Wn : Ws) + (size_t)m * 16384 + kk * DD + n);
    d_Wt[i] = __uint_as_float(f2tf32(v));
}

// ======================= gather (CSR mean aggregation, no atomics) =======================
__global__ void gather_kernel(const float* __restrict__ x, int use_x) {
    const float* hin = use_x ? x : d_h;
    int w = (blockIdx.x * blockDim.x + threadIdx.x) >> 5;
    int lane = threadIdx.x & 31;
    if (w >= NROWS) return;
    int o0 = __ldg(&d_rowoff[w]);
    int o1 = __ldg(&d_rowoff[w + 1]);
    float4 a = make_float4(0.f, 0.f, 0.f, 0.f);
    int s = (o0 < o1) ? __ldg(&d_esrc[o0]) : 0;
    for (int e = o0; e < o1; e++) {
        int sn = (e + 1 < o1) ? __ldg(&d_esrc[e + 1]) : 0;
        float4 v = __ldg(reinterpret_cast<const float4*>(hin + (size_t)s * DD) + lane);
        a.x += v.x; a.y += v.y; a.z += v.z; a.w += v.w;
        s = sn;
    }
    float sc = d_invdeg[w];
    a.x *= sc; a.y *= sc; a.z *= sc; a.w *= sc;
    reinterpret_cast<float4*>(d_neigh)[(size_t)w * 32 + lane] = a;
}

// ======================= merged tf32 mma GEMM (all 3 etypes, fused BN-reduce) =======================

#define ASTRIDE 36
#define ATILE (128 * ASTRIDE)
#define SMEM_BYTES (4 * ATILE * 4)

__device__ __forceinline__ void ldsm4(uint32_t* r, uint32_t addr) {
    asm volatile("ldmatrix.sync.aligned.m8n8.x4.shared.b16 {%0,%1,%2,%3}, [%4];"
                 : "=r"(r[0]), "=r"(r[1]), "=r"(r[2]), "=r"(r[3]) : "r"(addr));
}
__device__ __forceinline__ void mma8(float* c, const uint32_t* a, uint32_t b0, uint32_t b1) {
    asm volatile("mma.sync.aligned.m16n8k8.row.col.f32.tf32.tf32.f32 "
                 "{%0,%1,%2,%3}, {%4,%5,%6,%7}, {%8,%9}, {%0,%1,%2,%3};"
                 : "+f"(c[0]), "+f"(c[1]), "+f"(c[2]), "+f"(c[3])
                 : "r"(a[0]), "r"(a[1]), "r"(a[2]), "r"(a[3]), "r"(b0), "r"(b1));
}

__device__ __forceinline__ void ldgA(float4* ra, const float* __restrict__ src,
                                     int m0, int koff, int tid) {
#pragma unroll
    for (int t = 0; t < 4; t++) {
        int c = tid + t * 256;
        int gr = m0 + (c >> 3);
        ra[t] = (gr < NN)
            ? __ldg(reinterpret_cast<const float4*>(src + (size_t)gr * DD + koff) + (c & 7))
            : make_float4(0.f, 0.f, 0.f, 0.f);
    }
}
__device__ __forceinline__ void ldgB(float4* rb, const float* __restrict__ W,
                                     int koff, int tid) {
#pragma unroll
    for (int t = 0; t < 4; t++) {
        int c = tid + t * 256;
        rb[t] = __ldg(reinterpret_cast<const float4*>(W + (size_t)(c >> 3) * DD + koff) + (c & 7));
    }
}
__device__ __forceinline__ void stsA(float* As, const float4* ra, int tid) {
#pragma unroll
    for (int t = 0; t < 4; t++) {
        int c = tid + t * 256;
        uint4 u;
        u.x = f2tf32(ra[t].x); u.y = f2tf32(ra[t].y);
        u.z = f2tf32(ra[t].z); u.w = f2tf32(ra[t].w);
        *reinterpret_cast<uint4*>(As + (c >> 3) * ASTRIDE + (c & 7) * 4) = u;
    }
}
__device__ __forceinline__ void stsB(float* Bs, const float4* rb, int tid) {
#pragma unroll
    for (int t = 0; t < 4; t++) {
        int c = tid + t * 256;
        *reinterpret_cast<float4*>(Bs + (c >> 3) * ASTRIDE + (c & 7) * 4) = rb[t];
    }
}

__global__ void __launch_bounds__(256)
gemm_merged_kernel(const float* __restrict__ x, int use_x, int layer,
                   const float* __restrict__ bias, int do_relu) {
    extern __shared__ float sm[];
    float* Abuf[2] = { sm, sm + ATILE };
    float* Bbuf[2] = { sm + 2 * ATILE, sm + 3 * ATILE };
    uint32_t smb = (uint32_t)__cvta_generic_to_shared(sm);
    uint32_t asu[2] = { smb, smb + ATILE * 4 };
    uint32_t bsu[2] = { smb + 2 * ATILE * 4, smb + 3 * ATILE * 4 };

    const float* hin = use_x ? x : d_h;
    const float* Wl = d_Wt + (size_t)layer * NET * 2 * DD * DD;
    float* stats = d_stats3 + layer * 2 * DD;

    int tid = threadIdx.x, lane = tid & 31, wid = tid >> 5;
    int wm = wid & 3, wn = wid >> 2;
    int m0 = blockIdx.x * 128;

    uint32_t aoffb[2];
#pragma unroll
    for (int mf = 0; mf < 2; mf++)
        aoffb[mf] = ((wm * 32 + mf * 16 + (lane & 15)) * ASTRIDE + (lane >> 4) * 4) * 4;
    uint32_t boffb[4];
#pragma unroll
    for (int nf2 = 0; nf2 < 4; nf2++) {
        int n = wn * 64 + nf2 * 16 + (lane & 7) + ((lane >> 4) << 3);
        boffb[nf2] = (n * ASTRIDE + ((lane >> 3) & 1) * 4) * 4;
    }

    float facc[2][8][4], acc[2][8][4];
#pragma unroll
    for (int i = 0; i < 2; i++)
#pragma unroll
        for (int j = 0; j < 8; j++)
#pragma unroll
            for (int e = 0; e < 4; e++) { facc[i][j][e] = 0.f; acc[i][j][e] = 0.f; }

    float4 ra[4], rb[4];
    ldgA(ra, hin, m0, 0, tid);
    ldgB(rb, Wl, 0, tid);
    stsA(Abuf[0], ra, tid);
    stsB(Bbuf[0], rb, tid);
    __syncthreads();

#pragma unroll
    for (int t = 0; t < 24; t++) {
        const int cur = t & 1;
        if (t < 23) {
            const int tn = t + 1, pn = tn >> 2;
            const float* Asrc = (pn & 1) ? (d_neigh + (size_t)(pn >> 1) * NN * DD) : hin;
            ldgA(ra, Asrc, m0, (tn & 3) * 32, tid);
            ldgB(rb, Wl + (size_t)pn * DD * DD, (tn & 3) * 32, tid);
        }
#pragma unroll
        for (int ks = 0; ks < 4; ks++) {
            uint32_t af[2][4];
            ldsm4(af[0], asu[cur] + aoffb[0] + ks * 32);
            ldsm4(af[1], asu[cur] + aoffb[1] + ks * 32);
            uint32_t bf[4][4];
#pragma unroll
            for (int nf2 = 0; nf2 < 4; nf2++)
                ldsm4(bf[nf2], bsu[cur] + boffb[nf2] + ks * 32);
#pragma unroll
            for (int mf = 0; mf < 2; mf++)
#pragma unroll
                for (int nf = 0; nf < 8; nf++) {
                    int q = (nf & 1) * 2;
                    mma8(acc[mf][nf], af[mf], bf[nf >> 1][q], bf[nf >> 1][q + 1]);
                }
        }
        if (t == 7 || t == 15 || t == 23) {
            const float* be = bias + (t >> 3) * DD;
#pragma unroll
            for (int nf = 0; nf < 8; nf++) {
                int n = wn * 64 + nf * 8 + ((lane & 3) << 1);
                float b0 = __ldg(be + n), b1 = __ldg(be + n + 1);
#pragma unroll
                for (int mf = 0; mf < 2; mf++) {
                    float v0 = acc[mf][nf][0] + b0, v1 = acc[mf][nf][1] + b1;
                    float v2 = acc[mf][nf][2] + b0, v3 = acc[mf][nf][3] + b1;
                    if (do_relu) {
                        v0 = fmaxf(v0, 0.f); v1 = fmaxf(v1, 0.f);
                        v2 = fmaxf(v2, 0.f); v3 = fmaxf(v3, 0.f);
                    }
                    facc[mf][nf][0] += v0; facc[mf][nf][1] += v1;
                    facc[mf][nf][2] += v2; facc[mf][nf][3] += v3;
                    acc[mf][nf][0] = 0.f; acc[mf][nf][1] = 0.f;
                    acc[mf][nf][2] = 0.f; acc[mf][nf][3] = 0.f;
                }
            }
        }
        if (t < 23) {
            __syncthreads();
            stsA(Abuf[1 - cur], ra, tid);
            stsB(Bbuf[1 - cur], rb, tid);
            __syncthreads();
        }
    }

    int r0 = m0 + wm * 32 + (lane >> 2);
    int rr[2] = { r0, r0 + 16 };
#pragma unroll
    for (int nf = 0; nf < 8; nf++) {
        int n = wn * 64 + nf * 8 + ((lane & 3) << 1);
        float s0 = 0.f, s1 = 0.f, q0 = 0.f, q1 = 0.f;
#pragma unroll
        for (int mf = 0; mf < 2; mf++) {
            int r = rr[mf];
            float v0 = facc[mf][nf][0], v1 = facc[mf][nf][1];
            float v2 = facc[mf][nf][2], v3 = facc[mf][nf][3];
            if (r < NN) {
                *reinterpret_cast<float2*>(d_acc + (size_t)r * DD + n) = make_float2(v0, v1);
                s0 += v0; s1 += v1;
                q0 = fmaf(v0, v0, q0); q1 = fmaf(v1, v1, q1);
            }
            if (r + 8 < NN) {
                *reinterpret_cast<float2*>(d_acc + (size_t)(r + 8) * DD + n) = make_float2(v2, v3);
                s0 += v2; s1 += v3;
                q0 = fmaf(v2, v2, q0); q1 = fmaf(v3, v3, q1);
            }
        }
#pragma unroll
        for (int o = 4; o < 32; o <<= 1) {
            s0 += __shfl_xor_sync(0xFFFFFFFFu, s0, o);
            s1 += __shfl_xor_sync(0xFFFFFFFFu, s1, o);
            q0 += __shfl_xor_sync(0xFFFFFFFFu, q0, o);
            q1 += __shfl_xor_sync(0xFFFFFFFFu, q1, o);
        }
        if (lane < 4) {
            atomicAdd(stats + n, s0);
            atomicAdd(stats + n + 1, s1);
            atomicAdd(stats + DD + n, q0);
            atomicAdd(stats + DD + n + 1, q1);
        }
    }
}

// ======================= BatchNorm normalize =======================

__global__ void bn_norm_kernel(const float* __restrict__ gamma,
                               const float* __restrict__ beta,
                               float* __restrict__ outp, int write_out, int layer) {
    __shared__ float scale_s[DD];
    __shared__ float shift_s[DD];
    if (threadIdx.x < DD) {
        int c = threadIdx.x;
        const float* stats = d_stats3 + layer * 2 * DD;
        float mu = stats[c] * (1.0f / NN);
        float var = stats[DD + c] * (1.0f / NN) - mu * mu;
        float sc = __ldg(gamma + c) * rsqrtf(var + EPS);
        scale_s[c] = sc;
        shift_s[c] = __ldg(beta + c) - mu * sc;
    }
    __syncthreads();
    float* dstp = write_out ? outp : d_h;
    size_t i = (size_t)blockIdx.x * blockDim.x + threadIdx.x;
    if (i >= (size_t)NN * DD / 4) return;
    int col = (int)((i * 4) & (DD - 1));
    float4 v = reinterpret_cast<const float4*>(d_acc)[i];
    float4 o;
    o.x = v.x * scale_s[col + 0] + shift_s[col + 0];
    o.y = v.y * scale_s[col + 1] + shift_s[col + 1];
    o.z = v.z * scale_s[col + 2] + shift_s[col + 2];
    o.w = v.w * scale_s[col + 3] + shift_s[col + 3];
    reinterpret_cast<float4*>(dstp)[i] = o;
}

// ======================= launch =======================

extern "C" void kernel_launch(void* const* d_in, const int* in_sizes, int n_in,
                              void* d_out, int out_size) {
    const float* x     = (const float*)d_in[0];
    const int*   src   = (const int*)d_in[1];
    const int*   dst   = (const int*)d_in[2];
    const float* Ws    = (const float*)d_in[3];
    const float* Wn    = (const float*)d_in[4];
    const float* bias  = (const float*)d_in[5];
    const float* gamma = (const float*)d_in[6];
    const float* beta  = (const float*)d_in[7];
    float* out = (float*)d_out;

    cudaFuncSetAttribute(gemm_merged_kernel,
                         cudaFuncAttributeMaxDynamicSharedMemorySize, SMEM_BYTES);

    // weight prep
    {
        int n = NL * NET * 2 * DD * DD;
        wt_prep_kernel<<<(n + 255) / 256, 256>>>(Ws, Wn);
    }
    // CSR build
    {
        zero_cnt_kernel<<<(NROWS + 255) / 256, 256>>>();
        int ne = NET * NE;
        deg_count_kernel<<<(ne + 255) / 256, 256>>>(dst);
        scan1_kernel<<<SCAN_BLK, 256>>>();
        scan2_kernel<<<1, 512>>>();
        scan3_kernel<<<SCAN_BLK, 256>>>();
        permute_kernel<<<(ne + 255) / 256, 256>>>(src, dst);
    }

    const int gemm_blocks = (NN + 127) / 128;
    const int gather_blocks = (NROWS * 32 + 255) / 256;  // 37500
    const int bn4_blocks = (NN * DD / 4 + 255) / 256;

    for (int l = 0; l < NL; l++) {
        int use_x = (l == 0);
        int do_relu = (l < NL - 1);
        gather_kernel<<<gather_blocks, 256>>>(x, use_x);
        gemm_merged_kernel<<<gemm_blocks, 256, SMEM_BYTES>>>(
            x, use_x, l, bias + (size_t)l * NET * DD, do_relu);
        bn_norm_kernel<<<bn4_blocks, 256>>>(gamma + l * DD, beta + l * DD,
                                            out, (l == NL - 1), l);
    }
}